// round 8
// baseline (speedup 1.0000x reference)
#include <cuda_runtime.h>
#include <cstdint>

#define DIM   512
#define CDIM  12
#define NTOK  16384
#define CSIZE 4096
#define GRIDN 296                 // 2 CTAs/SM x 148 SMs, single wave
#define BLK   256
#define TPT   16                  // tokens per tile (8 warps x 2)
#define NTILE (NTOK / TPT)        // 1024

#define OUT_OFF_IDX (NTOK * DIM)            // 8388608
#define OUT_OFF_AUX (OUT_OFF_IDX + NTOK)    // 8404992
#define LOG_EPS_NEG 11.512925464970229f     // -ln(1e-5)
#define A_MAX       20.723265837f           // ln(1e9)
#define FULL        0xffffffffu

// dynamic smem layout (float index): w_out^T | bm | bp | x double buffer
#define SM_WT 0
#define SM_BM 6144
#define SM_BP 6656
#define SM_X  7168                // 2 buffers x 8192 floats (32KB each)
#define SM_FLTS (SM_X + 2 * TPT * DIM)
#define SM_BYTES (SM_FLTS * 4)    // 94208 B

// ---- device scratch (no allocations allowed) ----
__device__ float g_avg[CSIZE];
__device__ float g_pse;
__device__ int   g_flag = 0;
__device__ int   g_cnt  = 0;
__device__ int   g_tile = 0;      // dynamic tile counter

typedef unsigned long long u64;

__device__ __forceinline__ u64 fma2(u64 a, u64 b, u64 c) {
    u64 d; asm("fma.rn.f32x2 %0, %1, %2, %3;" : "=l"(d) : "l"(a), "l"(b), "l"(c));
    return d;
}
__device__ __forceinline__ u64 add2(u64 a, u64 b) {
    u64 d; asm("add.rn.f32x2 %0, %1, %2;" : "=l"(d) : "l"(a), "l"(b));
    return d;
}
__device__ __forceinline__ u64 pack2(float lo, float hi) {
    u64 d; asm("mov.b64 %0, {%1, %2};" : "=l"(d) : "f"(lo), "f"(hi));
    return d;
}
__device__ __forceinline__ float fold2(u64 v) {   // lo + hi
    float lo, hi; asm("mov.b64 {%0, %1}, %2;" : "=f"(lo), "=f"(hi) : "l"(v));
    return lo + hi;
}

// cp.async one 16-token tile (32KB) into buffer buf; one commit group.
__device__ __forceinline__ void fetch_tile(const float* __restrict__ x,
                                           float* sm, int buf, int tile) {
    uint32_t base = (uint32_t)__cvta_generic_to_shared(sm + SM_X)
                  + (uint32_t)buf * (TPT * DIM * 4);
    const float4* src = (const float4*)(x + (size_t)tile * (TPT * DIM));
    const int tid = threadIdx.x;
#pragma unroll
    for (int j = 0; j < (TPT * DIM / 4) / BLK; j++) {   // 8 iters
        int idx = j * BLK + tid;
        asm volatile("cp.async.cg.shared.global [%0], [%1], 16;"
                     :: "r"(base + (uint32_t)idx * 16), "l"(src + idx));
    }
    asm volatile("cp.async.commit_group;" ::: "memory");
}

// ---------------------------------------------------------------------------
__global__ void __launch_bounds__(BLK)
mainK(const float* __restrict__ x,
      const float* __restrict__ w_in,
      const float* __restrict__ b_in,
      const float* __restrict__ w_out,
      const float* __restrict__ b_out,
      float* __restrict__ out)
{
    extern __shared__ float sm[];
    float* s_wt = sm + SM_WT;
    float* s_bm = sm + SM_BM;
    float* s_bp = sm + SM_BP;
    __shared__ int s_tile, s_last;

    // grab first tile immediately and start streaming x before anything else
    if (threadIdx.x == 0) s_tile = atomicAdd(&g_tile, 1);
    __syncthreads();
    int tile = s_tile;
    int buf  = 0;
    if (tile < NTILE) fetch_tile(x, sm, 0, tile);

    // block 0 zeros cross-block accumulators (overlaps with tile 0 flight)
    if (blockIdx.x == 0) {
        for (int i = threadIdx.x; i < CSIZE; i += BLK) g_avg[i] = 0.f;
        if (threadIdx.x == 0) g_pse = 0.f;
    }
    // stage w_out^T and b_out -+ S
    for (int d = threadIdx.x; d < DIM; d += BLK) {
        float S = 0.f;
#pragma unroll
        for (int c = 0; c < CDIM; c++) {
            float w = w_out[d * CDIM + c];
            s_wt[c * DIM + d] = w;
            S += w;
        }
        float b = b_out[d];
        s_bm[d] = b - S;
        s_bp[d] = b + S;
    }
    __syncthreads();
    if (blockIdx.x == 0 && threadIdx.x == 0) {
        __threadfence();
        atomicExch(&g_flag, 1);
    }

    const int wid   = threadIdx.x >> 5;
    const int lane  = threadIdx.x & 31;
    const int c_own = (lane >> 1) & 15;
    const float b_lane = (c_own < CDIM) ? __ldg(&b_in[c_own]) : 0.f;

    const ulonglong2* W2g = (const ulonglong2*)w_in;     // L1-resident
    const ulonglong2* WT2 = (const ulonglong2*)s_wt;
    const ulonglong2* SX2 = (const ulonglong2*)(sm + SM_X);
    ulonglong2*       O2  = (ulonglong2*)out;

    float pse_acc = 0.f;
    bool  flagged = false;

    while (tile < NTILE) {
        // grab + prefetch next tile, then wait for current
        if (threadIdx.x == 0) s_tile = atomicAdd(&g_tile, 1);
        __syncthreads();                       // s_tile visible; old buffer free
        const int nxt = s_tile;
        if (nxt < NTILE) {
            fetch_tile(x, sm, buf ^ 1, nxt);
            asm volatile("cp.async.wait_group 1;" ::: "memory");
        } else {
            asm volatile("cp.async.wait_group 0;" ::: "memory");
        }
        __syncthreads();                       // current tile visible to all

        // ================= compute this tile (2 tokens per warp) ===========
        const int tok0 = tile * TPT + wid * 2;
        const ulonglong2* XB = SX2 + (size_t)buf * (TPT * DIM / 4)
                                   + (size_t)(wid * 2) * 128;

        // ---- in-projection: single pass, packed FFMA2 ----
        u64 a2[2][CDIM];
#pragma unroll
        for (int c = 0; c < CDIM; c++) { a2[0][c] = 0ull; a2[1][c] = 0ull; }
#pragma unroll
        for (int i = 0; i < 4; i++) {
            ulonglong2 x0 = XB[i * 32 + lane];
            ulonglong2 x1 = XB[128 + i * 32 + lane];
#pragma unroll
            for (int c = 0; c < CDIM; c++) {
                ulonglong2 w = __ldg(&W2g[c * 128 + i * 32 + lane]);
                a2[0][c] = fma2(x0.x, w.x, a2[0][c]);
                a2[0][c] = fma2(x0.y, w.y, a2[0][c]);
                a2[1][c] = fma2(x1.x, w.x, a2[1][c]);
                a2[1][c] = fma2(x1.y, w.y, a2[1][c]);
            }
        }
        float vv[2][CDIM];
#pragma unroll
        for (int c = 0; c < CDIM; c++) {
            vv[0][c] = fold2(a2[0][c]);
            vv[1][c] = fold2(a2[1][c]);
        }

        // ---- per-token: reduce-scatter -> ballots -> entropy -> out-proj --
#pragma unroll
        for (int t = 0; t < 2; t++) {
            float r8[8];
#pragma unroll
            for (int j = 0; j < 8; j++) {
                float hiV  = (j + 8 < CDIM) ? vv[t][j + 8] : 0.f;
                float send = (lane & 16) ? vv[t][j] : hiV;
                float keep = (lane & 16) ? hiV : vv[t][j];
                r8[j] = keep + __shfl_xor_sync(FULL, send, 16);
            }
            float r4[4];
#pragma unroll
            for (int j = 0; j < 4; j++) {
                float send = (lane & 8) ? r8[j] : r8[j + 4];
                float keep = (lane & 8) ? r8[j + 4] : r8[j];
                r4[j] = keep + __shfl_xor_sync(FULL, send, 8);
            }
            float r2[2];
#pragma unroll
            for (int j = 0; j < 2; j++) {
                float send = (lane & 4) ? r4[j] : r4[j + 2];
                float keep = (lane & 4) ? r4[j + 2] : r4[j];
                r2[j] = keep + __shfl_xor_sync(FULL, send, 4);
            }
            float send = (lane & 2) ? r2[0] : r2[1];
            float keep = (lane & 2) ? r2[1] : r2[0];
            float r1 = keep + __shfl_xor_sync(FULL, send, 2);
            r1 += __shfl_xor_sync(FULL, r1, 1);

            const float xp = r1 + b_lane;           // xp for c_own
            const float a  = 400.f * fabsf(xp);

            unsigned sb  = __ballot_sync(FULL, xp > 0.f);
            unsigned act = __ballot_sync(FULL, a < A_MAX) & 0x00555555u;

            unsigned e = sb & 0x00555555u;          // compress even bits
            e = (e | (e >> 1)) & 0x33333333u;
            e = (e | (e >> 2)) & 0x0F0F0F0Fu;
            e = (e | (e >> 4)) & 0x00FF00FFu;
            e = (e | (e >> 8)) & 0x0000FFFFu;
            const int idx = (int)(__brev(e) >> 20);

            if (lane == 0) out[OUT_OFF_IDX + tok0 + t] = (float)idx;

            if (!flagged) {
                while (*(volatile int*)&g_flag == 0) { }
                flagged = true;
            }

            // ---- entropy (factorized softmax) ----
            if (act == 0u) {
                if (lane == 0) atomicAdd(&g_avg[idx], 1.f);
            } else {
                const int k = __popc(act);
                float Z = 1.f;
                unsigned mm = act;
                while (mm) {
                    int b = __ffs(mm) - 1;
                    float ac = __shfl_sync(FULL, a, b);
                    Z *= 1.f + __expf(-ac);
                    mm &= mm - 1;
                }
                const float logZ = __logf(Z);
                const float invZ = 1.f / Z;
                const int   n    = 1 << k;
                for (int base = 0; base < n; base += 32) {
                    const int sub = base + lane;
                    float Asum = 0.f;
                    int   ix   = idx, j = 0;
                    mm = act;
                    while (mm) {
                        int b = __ffs(mm) - 1;
                        int c = b >> 1;
                        float ac = __shfl_sync(FULL, a, b);
                        if ((sub >> j) & 1) { Asum += ac; ix ^= 1 << (11 - c); }
                        mm &= mm - 1; j++;
                    }
                    if (sub < n) {
                        float pp = invZ * __expf(-Asum);
                        pse_acc += pp * fminf(Asum + logZ, LOG_EPS_NEG);
                        atomicAdd(&g_avg[ix], pp);
                    }
                }
            }

            // ---- sparse out-projection ----
            const int pc = __popc((unsigned)idx);
            unsigned bits = (pc <= 6) ? (unsigned)idx : (~(unsigned)idx & 0xFFFu);
            const float* bb = (pc <= 6) ? s_bm : s_bp;
            const u64 coef  = pack2(pc <= 6 ? 2.f : -2.f, pc <= 6 ? 2.f : -2.f);

            u64 o[8];
#pragma unroll
            for (int i = 0; i < 8; i++) o[i] = 0ull;
            while (bits) {
                int b = __ffs(bits) - 1;
                int c = 11 - b;
                const ulonglong2* W = WT2 + c * 128;
#pragma unroll
                for (int i = 0; i < 4; i++) {
                    ulonglong2 w = W[i * 32 + lane];
                    o[2 * i]     = add2(o[2 * i],     w.x);
                    o[2 * i + 1] = add2(o[2 * i + 1], w.y);
                }
                bits &= bits - 1;
            }
            const ulonglong2* B2 = (const ulonglong2*)bb;
#pragma unroll
            for (int i = 0; i < 4; i++) {
                ulonglong2 bv = B2[i * 32 + lane];
                ulonglong2 res;
                res.x = fma2(coef, o[2 * i],     bv.x);
                res.y = fma2(coef, o[2 * i + 1], bv.y);
                O2[(size_t)(tok0 + t) * 128 + i * 32 + lane] = res;
            }
        }
        // ===================================================================
        tile = nxt;
        buf ^= 1;
    }

    // ---- reduce pse: warp, block, global ----
    pse_acc += __shfl_xor_sync(FULL, pse_acc, 16);
    pse_acc += __shfl_xor_sync(FULL, pse_acc, 8);
    pse_acc += __shfl_xor_sync(FULL, pse_acc, 4);
    pse_acc += __shfl_xor_sync(FULL, pse_acc, 2);
    pse_acc += __shfl_xor_sync(FULL, pse_acc, 1);

    __syncthreads();                 // all warps past tile loop; smem reusable
    if (lane == 0) s_bm[wid] = pse_acc;
    __syncthreads();
    if (wid == 0) {
        float v = (lane < (BLK >> 5)) ? s_bm[lane] : 0.f;
        v += __shfl_xor_sync(FULL, v, 4);
        v += __shfl_xor_sync(FULL, v, 2);
        v += __shfl_xor_sync(FULL, v, 1);
        if (lane == 0) atomicAdd(&g_pse, v);
    }

    // ---- last-block finalize ----
    __threadfence();
    __syncthreads();
    if (threadIdx.x == 0) {
        int old = atomicAdd(&g_cnt, 1);
        s_last = (old == (int)gridDim.x - 1) ? 1 : 0;
    }
    __syncthreads();
    if (s_last) {
        __threadfence();
        const float inv = 1.f / (float)NTOK;
        float ce = 0.f;
        for (int i = threadIdx.x; i < CSIZE; i += BLK) {
            float ap = __ldcg(&g_avg[i]) * inv;
            ce += -ap * __logf(fmaxf(ap, 1e-5f));
        }
        float* red = s_wt;
        red[threadIdx.x] = ce;
        __syncthreads();
        for (int s = BLK / 2; s > 0; s >>= 1) {
            if (threadIdx.x < (unsigned)s) red[threadIdx.x] += red[threadIdx.x + s];
            __syncthreads();
        }
        if (threadIdx.x == 0) {
            float aux = (__ldcg(&g_pse) * inv - red[0]) * 0.1f;
            out[OUT_OFF_AUX] = aux;
            g_cnt  = 0;      // reset for next graph replay
            g_flag = 0;
            g_tile = 0;
        }
    }
}

// ---------------------------------------------------------------------------
extern "C" void kernel_launch(void* const* d_in, const int* in_sizes, int n_in,
                              void* d_out, int out_size)
{
    const float* x     = (const float*)d_in[0];
    const float* w_in  = (const float*)d_in[1];
    const float* b_in  = (const float*)d_in[2];
    const float* w_out = (const float*)d_in[3];
    const float* b_out = (const float*)d_in[4];
    float* out = (float*)d_out;

    cudaFuncSetAttribute(mainK, cudaFuncAttributeMaxDynamicSharedMemorySize,
                         SM_BYTES);
    mainK<<<GRIDN, BLK, SM_BYTES>>>(x, w_in, b_in, w_out, b_out, out);
}

// round 9
// speedup vs baseline: 1.0768x; 1.0768x over previous
#include <cuda_runtime.h>
#include <cstdint>

#define DIM   512
#define CDIM  12
#define NTOK  16384
#define CSIZE 4096
#define GRIDN 1024
#define BLK   256

#define OUT_OFF_IDX (NTOK * DIM)            // 8388608
#define OUT_OFF_AUX (OUT_OFF_IDX + NTOK)    // 8404992
#define LOG_EPS_NEG 11.512925464970229f     // -ln(1e-5)
#define A_MAX       20.723265837f           // ln(1e9)
#define FULL        0xffffffffu

// dynamic smem (floats): w_out^T [12][512] | x slots: 8 warps x 1024
#define SM_WT   0
#define SM_X    6144
#define SM_FLTS (SM_X + 8 * 2 * DIM)        // 14336 floats
#define SM_BYTES (SM_FLTS * 4)              // 57344 B

// ---- device scratch (no allocations allowed) ----
__device__ float g_avg[CSIZE];
__device__ float g_pse;
__device__ int   g_flag = 0;
__device__ int   g_cnt  = 0;

typedef unsigned long long u64;

__device__ __forceinline__ u64 fma2(u64 a, u64 b, u64 c) {
    u64 d; asm("fma.rn.f32x2 %0, %1, %2, %3;" : "=l"(d) : "l"(a), "l"(b), "l"(c));
    return d;
}
__device__ __forceinline__ float fold2(u64 v) {   // lo + hi
    float lo, hi; asm("mov.b64 {%0, %1}, %2;" : "=f"(lo), "=f"(hi) : "l"(v));
    return lo + hi;
}
__device__ __forceinline__ ulonglong2 ldg2(const ulonglong2* p) {
    ulonglong2 r;
    asm("ld.global.nc.v2.u64 {%0, %1}, [%2];" : "=l"(r.x), "=l"(r.y) : "l"(p));
    return r;
}

// ---------------------------------------------------------------------------
// grid 1024 x block 256 (4 CTAs/SM), 56KB dynamic smem.
// Per warp: 2 tokens. x prefetched per-warp via cp.async.cg (L1-bypass, no
// block barriers). In-proj: packed FFMA2, w_in via LDG (L1-resident).
// Scatter trees of both tokens interleaved level-major. Entropy: factorized
// softmax, warp-parallel. Out-proj: dense unrolled FFMA, w_out^T from smem
// shared across the pair — no data-dependent loops.
// ---------------------------------------------------------------------------
__global__ void __launch_bounds__(BLK, 4)
mainK(const float* __restrict__ x,
      const float* __restrict__ w_in,
      const float* __restrict__ b_in,
      const float* __restrict__ w_out,
      const float* __restrict__ b_out,
      float* __restrict__ out)
{
    extern __shared__ float sm[];
    float* s_wt = sm + SM_WT;
    __shared__ float s_red[8];
    __shared__ int   s_last;

    const int wid  = threadIdx.x >> 5;
    const int lane = threadIdx.x & 31;
    const int gw   = blockIdx.x * (BLK >> 5) + wid;   // 0..8191
    const int tok0 = gw * 2;

    // ---- per-warp cp.async prefetch of this warp's 2 tokens (4KB) ----
    {
        uint32_t dst = (uint32_t)__cvta_generic_to_shared(sm + SM_X + wid * 1024);
        const float4* src = (const float4*)(x + (size_t)tok0 * DIM);
#pragma unroll
        for (int j = 0; j < 8; j++) {
            int idx = j * 32 + lane;
            asm volatile("cp.async.cg.shared.global [%0], [%1], 16;"
                         :: "r"(dst + (uint32_t)idx * 16), "l"(src + idx));
        }
        asm volatile("cp.async.commit_group;" ::: "memory");
    }

    // block 0 zeros cross-block accumulators (overlaps x flight)
    if (blockIdx.x == 0) {
        for (int i = threadIdx.x; i < CSIZE; i += BLK) g_avg[i] = 0.f;
        if (threadIdx.x == 0) g_pse = 0.f;
    }
    // stage w_out^T (overlaps x flight)
    for (int d = threadIdx.x; d < DIM; d += BLK) {
#pragma unroll
        for (int c = 0; c < CDIM; c++)
            s_wt[c * DIM + d] = w_out[d * CDIM + c];
    }
    __syncthreads();
    if (blockIdx.x == 0 && threadIdx.x == 0) {
        __threadfence();
        atomicExch(&g_flag, 1);
    }

    const int c_own = (lane >> 1) & 15;
    const float b_lane = (c_own < CDIM) ? __ldg(&b_in[c_own]) : 0.f;

    const ulonglong2* W2g = (const ulonglong2*)w_in;   // L1-resident (cg bypass)
    const ulonglong2* XB  = (const ulonglong2*)(sm + SM_X + wid * 1024);
    const float4*     WT4 = (const float4*)s_wt;
    float4*           O4  = (float4*)out;

    float pse_acc = 0.f;

    // wait for this warp's x (per-warp, no block barrier)
    asm volatile("cp.async.wait_group 0;" ::: "memory");
    __syncwarp();

    // ---- in-projection: packed FFMA2, chunked over c (6 at a time) ----
    float vv[2][CDIM];
#pragma unroll
    for (int ch = 0; ch < 2; ch++) {
        u64 a2[2][6];
#pragma unroll
        for (int cc = 0; cc < 6; cc++) { a2[0][cc] = 0ull; a2[1][cc] = 0ull; }
#pragma unroll
        for (int i = 0; i < 4; i++) {
            ulonglong2 x0 = XB[i * 32 + lane];
            ulonglong2 x1 = XB[128 + i * 32 + lane];
#pragma unroll
            for (int cc = 0; cc < 6; cc++) {
                ulonglong2 w = ldg2(&W2g[(ch * 6 + cc) * 128 + i * 32 + lane]);
                a2[0][cc] = fma2(x0.x, w.x, a2[0][cc]);
                a2[0][cc] = fma2(x0.y, w.y, a2[0][cc]);
                a2[1][cc] = fma2(x1.x, w.x, a2[1][cc]);
                a2[1][cc] = fma2(x1.y, w.y, a2[1][cc]);
            }
        }
#pragma unroll
        for (int cc = 0; cc < 6; cc++) {
            vv[0][ch * 6 + cc] = fold2(a2[0][cc]);
            vv[1][ch * 6 + cc] = fold2(a2[1][cc]);
        }
    }

    // ---- reduce-scatter, BOTH tokens interleaved level-major ----
    float r8[2][8];
#pragma unroll
    for (int j = 0; j < 8; j++)
#pragma unroll
        for (int t = 0; t < 2; t++) {
            float hiV  = (j + 8 < CDIM) ? vv[t][j + 8] : 0.f;
            float send = (lane & 16) ? vv[t][j] : hiV;
            float keep = (lane & 16) ? hiV : vv[t][j];
            r8[t][j] = keep + __shfl_xor_sync(FULL, send, 16);
        }
    float r4[2][4];
#pragma unroll
    for (int j = 0; j < 4; j++)
#pragma unroll
        for (int t = 0; t < 2; t++) {
            float send = (lane & 8) ? r8[t][j] : r8[t][j + 4];
            float keep = (lane & 8) ? r8[t][j + 4] : r8[t][j];
            r4[t][j] = keep + __shfl_xor_sync(FULL, send, 8);
        }
    float r2[2][2];
#pragma unroll
    for (int j = 0; j < 2; j++)
#pragma unroll
        for (int t = 0; t < 2; t++) {
            float send = (lane & 4) ? r4[t][j] : r4[t][j + 2];
            float keep = (lane & 4) ? r4[t][j + 2] : r4[t][j];
            r2[t][j] = keep + __shfl_xor_sync(FULL, send, 4);
        }
    float xp2[2], aa2[2];
    int   idx2[2];
    unsigned act2[2];
#pragma unroll
    for (int t = 0; t < 2; t++) {
        float send = (lane & 2) ? r2[t][0] : r2[t][1];
        float keep = (lane & 2) ? r2[t][1] : r2[t][0];
        float r1 = keep + __shfl_xor_sync(FULL, send, 2);
        r1 += __shfl_xor_sync(FULL, r1, 1);
        xp2[t] = r1 + b_lane;
        aa2[t] = 400.f * fabsf(xp2[t]);

        unsigned sb = __ballot_sync(FULL, xp2[t] > 0.f);
        act2[t]     = __ballot_sync(FULL, aa2[t] < A_MAX) & 0x00555555u;

        unsigned e = sb & 0x00555555u;      // compress even bits, then reverse
        e = (e | (e >> 1)) & 0x33333333u;
        e = (e | (e >> 2)) & 0x0F0F0F0Fu;
        e = (e | (e >> 4)) & 0x00FF00FFu;
        e = (e | (e >> 8)) & 0x0000FFFFu;
        idx2[t] = (int)(__brev(e) >> 20);
        if (lane == 0) out[OUT_OFF_IDX + tok0 + t] = (float)idx2[t];
    }

    while (*(volatile int*)&g_flag == 0) { }

    // ---- entropy (factorized softmax), per token ----
#pragma unroll
    for (int t = 0; t < 2; t++) {
        const unsigned act = act2[t];
        const float    a   = aa2[t];
        const int      idx = idx2[t];
        if (act == 0u) {
            if (lane == 0) atomicAdd(&g_avg[idx], 1.f);
        } else {
            const int k = __popc(act);
            float Z = 1.f;
            unsigned mm = act;
            while (mm) {
                int b = __ffs(mm) - 1;
                float ac = __shfl_sync(FULL, a, b);
                Z *= 1.f + __expf(-ac);
                mm &= mm - 1;
            }
            const float logZ = __logf(Z);
            const float invZ = 1.f / Z;
            const int   n    = 1 << k;
            for (int base = 0; base < n; base += 32) {
                const int sub = base + lane;
                float Asum = 0.f;
                int   ix   = idx, j = 0;
                mm = act;
                while (mm) {
                    int b = __ffs(mm) - 1;
                    int c = b >> 1;
                    float ac = __shfl_sync(FULL, a, b);
                    if ((sub >> j) & 1) { Asum += ac; ix ^= 1 << (11 - c); }
                    mm &= mm - 1; j++;
                }
                if (sub < n) {
                    float pp = invZ * __expf(-Asum);
                    pse_acc += pp * fminf(Asum + logZ, LOG_EPS_NEG);
                    atomicAdd(&g_avg[ix], pp);
                }
            }
        }
    }

    // ---- out-projection: dense unrolled, w shared across the pair ----
    {
        float s0[CDIM], s1[CDIM];
#pragma unroll
        for (int c = 0; c < CDIM; c++) {
            s0[c] = ((idx2[0] >> (11 - c)) & 1) ? 1.f : -1.f;
            s1[c] = ((idx2[1] >> (11 - c)) & 1) ? 1.f : -1.f;
        }
#pragma unroll
        for (int i = 0; i < 4; i++) {
            const int off = i * 32 + lane;
            float4 bv = __ldg((const float4*)b_out + off);
            float4 o0 = bv, o1 = bv;
#pragma unroll
            for (int c = 0; c < CDIM; c++) {
                float4 w = WT4[c * 128 + off];
                o0.x += s0[c] * w.x; o0.y += s0[c] * w.y;
                o0.z += s0[c] * w.z; o0.w += s0[c] * w.w;
                o1.x += s1[c] * w.x; o1.y += s1[c] * w.y;
                o1.z += s1[c] * w.z; o1.w += s1[c] * w.w;
            }
            O4[(size_t)tok0 * 128 + off]       = o0;
            O4[(size_t)(tok0 + 1) * 128 + off] = o1;
        }
    }

    // ---- reduce pse: warp, block, global ----
    pse_acc += __shfl_xor_sync(FULL, pse_acc, 16);
    pse_acc += __shfl_xor_sync(FULL, pse_acc, 8);
    pse_acc += __shfl_xor_sync(FULL, pse_acc, 4);
    pse_acc += __shfl_xor_sync(FULL, pse_acc, 2);
    pse_acc += __shfl_xor_sync(FULL, pse_acc, 1);

    if (lane == 0) s_red[wid] = pse_acc;
    __syncthreads();
    if (wid == 0) {
        float v = (lane < (BLK >> 5)) ? s_red[lane] : 0.f;
        v += __shfl_xor_sync(FULL, v, 4);
        v += __shfl_xor_sync(FULL, v, 2);
        v += __shfl_xor_sync(FULL, v, 1);
        if (lane == 0) atomicAdd(&g_pse, v);
    }

    // ---- last-block finalize ----
    __threadfence();
    __syncthreads();
    if (threadIdx.x == 0) {
        int old = atomicAdd(&g_cnt, 1);
        s_last = (old == (int)gridDim.x - 1) ? 1 : 0;
    }
    __syncthreads();
    if (s_last) {
        __threadfence();
        const float inv = 1.f / (float)NTOK;
        float ce = 0.f;
        for (int i = threadIdx.x; i < CSIZE; i += BLK) {
            float ap = __ldcg(&g_avg[i]) * inv;
            ce += -ap * __logf(fmaxf(ap, 1e-5f));
        }
        float* red = s_wt;            // reuse smem
        red[threadIdx.x] = ce;
        __syncthreads();
        for (int s = BLK / 2; s > 0; s >>= 1) {
            if (threadIdx.x < (unsigned)s) red[threadIdx.x] += red[threadIdx.x + s];
            __syncthreads();
        }
        if (threadIdx.x == 0) {
            float aux = (__ldcg(&g_pse) * inv - red[0]) * 0.1f;
            out[OUT_OFF_AUX] = aux;
            g_cnt  = 0;               // reset for next graph replay
            g_flag = 0;
        }
    }
}

// ---------------------------------------------------------------------------
extern "C" void kernel_launch(void* const* d_in, const int* in_sizes, int n_in,
                              void* d_out, int out_size)
{
    const float* x     = (const float*)d_in[0];
    const float* w_in  = (const float*)d_in[1];
    const float* b_in  = (const float*)d_in[2];
    const float* w_out = (const float*)d_in[3];
    const float* b_out = (const float*)d_in[4];
    float* out = (float*)d_out;

    cudaFuncSetAttribute(mainK, cudaFuncAttributeMaxDynamicSharedMemorySize,
                         SM_BYTES);
    mainK<<<GRIDN, BLK, SM_BYTES>>>(x, w_in, b_in, w_out, b_out, out);
}

// round 11
// speedup vs baseline: 1.4820x; 1.3762x over previous
#include <cuda_runtime.h>

#define DIM   512
#define CDIM  12
#define NTOK  16384
#define CSIZE 4096
#define GRID  512
#define BLK   256
#define NPASS 2

#define OUT_OFF_IDX (NTOK * DIM)            // 8388608
#define OUT_OFF_AUX (OUT_OFF_IDX + NTOK)    // 8404992
#define LOG_EPS_NEG 11.512925464970229f     // -ln(1e-5)
#define A_MAX       20.723265837f           // ln(1e9)
#define FULL        0xffffffffu

// ---- device scratch (no allocations allowed) ----
__device__ float g_avg[CSIZE];
__device__ float g_pse;
__device__ int   g_flag = 0;
__device__ int   g_cnt  = 0;

typedef unsigned long long u64;

__device__ __forceinline__ u64 fma2(u64 a, u64 b, u64 c) {
    u64 d; asm("fma.rn.f32x2 %0, %1, %2, %3;" : "=l"(d) : "l"(a), "l"(b), "l"(c));
    return d;
}
__device__ __forceinline__ u64 add2(u64 a, u64 b) {
    u64 d; asm("add.rn.f32x2 %0, %1, %2;" : "=l"(d) : "l"(a), "l"(b));
    return d;
}
__device__ __forceinline__ u64 pack2(float lo, float hi) {
    u64 d; asm("mov.b64 %0, {%1, %2};" : "=l"(d) : "f"(lo), "f"(hi));
    return d;
}
__device__ __forceinline__ float fold2(u64 v) {   // lo + hi
    float lo, hi; asm("mov.b64 {%0, %1}, %2;" : "=f"(lo), "=f"(hi) : "l"(v));
    return lo + hi;
}

// ---------------------------------------------------------------------------
// R6 structure (best: 38.9us), entropy transcendentals moved to MUFU
// (__expf/__logf — verified rel_err-neutral in R8/R9). grid 512 x block 256
// (4 CTAs/SM), 28KB static smem. 4 tokens/warp. In-proj: FFMA2 packed,
// reduce-scatter + ballot; warp-parallel factorized-softmax entropy; sparse
// +-2w out-projection against precomputed (b_out -+ S).
// (Round 10 resubmission — previous bench was an infra failure, not a result.)
// ---------------------------------------------------------------------------
__global__ void __launch_bounds__(BLK, 4)
mainK(const float* __restrict__ x,
      const float* __restrict__ w_in,
      const float* __restrict__ b_in,
      const float* __restrict__ w_out,
      const float* __restrict__ b_out,
      float* __restrict__ out)
{
    __shared__ float s_wt[CDIM * DIM];   // w_out transposed [c][d]
    __shared__ float s_bm[DIM];          // b_out - S
    __shared__ float s_bp[DIM];          // b_out + S
    __shared__ int   s_last;

    if (blockIdx.x == 0) {
        for (int i = threadIdx.x; i < CSIZE; i += BLK) g_avg[i] = 0.f;
        if (threadIdx.x == 0) g_pse = 0.f;
    }

    // stage: transpose w_out, build b_out -+ S  (S = sum_c w_out[d][c])
    for (int d = threadIdx.x; d < DIM; d += BLK) {
        float S = 0.f;
#pragma unroll
        for (int c = 0; c < CDIM; c++) {
            float w = w_out[d * CDIM + c];
            s_wt[c * DIM + d] = w;
            S += w;
        }
        float b = b_out[d];
        s_bm[d] = b - S;
        s_bp[d] = b + S;
    }
    __syncthreads();

    if (blockIdx.x == 0 && threadIdx.x == 0) {
        __threadfence();
        atomicExch(&g_flag, 1);
    }

    const int wid   = threadIdx.x >> 5;
    const int lane  = threadIdx.x & 31;
    const int gw    = blockIdx.x * (BLK >> 5) + wid;   // 0..4095
    const int c_own = (lane >> 1) & 15;                // c owned by this lane
    const float b_lane = (c_own < CDIM) ? __ldg(&b_in[c_own]) : 0.f;

    const ulonglong2* X2  = (const ulonglong2*)x;
    const ulonglong2* W2  = (const ulonglong2*)w_in;
    const ulonglong2* WT2 = (const ulonglong2*)s_wt;
    ulonglong2*       O2  = (ulonglong2*)out;

    float pse_acc = 0.f;      // distributed across all lanes
    bool  flagged = false;

#pragma unroll
    for (int p = 0; p < NPASS; p++) {
        const int tok0 = gw * 4 + p * 2;

        // ---- in-projection: packed FFMA2, chunked over c (6 at a time) ----
        float vv[2][CDIM];
#pragma unroll
        for (int ch = 0; ch < 2; ch++) {
            u64 a2[2][6];
#pragma unroll
            for (int cc = 0; cc < 6; cc++) { a2[0][cc] = 0ull; a2[1][cc] = 0ull; }
#pragma unroll
            for (int i = 0; i < 4; i++) {
                const int off = i * 32 + lane;
                ulonglong2 x0 = X2[(size_t)tok0 * 128 + off];
                ulonglong2 x1 = X2[(size_t)(tok0 + 1) * 128 + off];
#pragma unroll
                for (int cc = 0; cc < 6; cc++) {
                    ulonglong2 w = W2[(ch * 6 + cc) * 128 + off];
                    a2[0][cc] = fma2(x0.x, w.x, a2[0][cc]);
                    a2[0][cc] = fma2(x0.y, w.y, a2[0][cc]);
                    a2[1][cc] = fma2(x1.x, w.x, a2[1][cc]);
                    a2[1][cc] = fma2(x1.y, w.y, a2[1][cc]);
                }
            }
#pragma unroll
            for (int cc = 0; cc < 6; cc++) {
                vv[0][ch * 6 + cc] = fold2(a2[0][cc]);
                vv[1][ch * 6 + cc] = fold2(a2[1][cc]);
            }
        }

        if (!flagged) {
            while (*(volatile int*)&g_flag == 0) { }
            flagged = true;
        }

        // ---- per-token: reduce-scatter -> ballots -> entropy -> out-proj ----
#pragma unroll
        for (int t = 0; t < 2; t++) {
            // reduce-scatter: sum over lanes; c lands on lanes 2c, 2c+1.
            float r8[8];
#pragma unroll
            for (int j = 0; j < 8; j++) {
                float hiV  = (j + 8 < CDIM) ? vv[t][j + 8] : 0.f;
                float send = (lane & 16) ? vv[t][j] : hiV;
                float keep = (lane & 16) ? hiV : vv[t][j];
                r8[j] = keep + __shfl_xor_sync(FULL, send, 16);
            }
            float r4[4];
#pragma unroll
            for (int j = 0; j < 4; j++) {
                float send = (lane & 8) ? r8[j] : r8[j + 4];
                float keep = (lane & 8) ? r8[j + 4] : r8[j];
                r4[j] = keep + __shfl_xor_sync(FULL, send, 8);
            }
            float r2[2];
#pragma unroll
            for (int j = 0; j < 2; j++) {
                float send = (lane & 4) ? r4[j] : r4[j + 2];
                float keep = (lane & 4) ? r4[j + 2] : r4[j];
                r2[j] = keep + __shfl_xor_sync(FULL, send, 4);
            }
            float send = (lane & 2) ? r2[0] : r2[1];
            float keep = (lane & 2) ? r2[1] : r2[0];
            float r1 = keep + __shfl_xor_sync(FULL, send, 2);
            r1 += __shfl_xor_sync(FULL, r1, 1);

            const float xp = r1 + b_lane;               // xp for c_own
            const float a  = 400.f * fabsf(xp);

            unsigned sb  = __ballot_sync(FULL, xp > 0.f);
            unsigned act = __ballot_sync(FULL, a < A_MAX) & 0x00555555u;

            // index: compress even bits of sb (bit 2c -> bit c), then reverse
            unsigned e = sb & 0x00555555u;
            e = (e | (e >> 1)) & 0x33333333u;
            e = (e | (e >> 2)) & 0x0F0F0F0Fu;
            e = (e | (e >> 4)) & 0x00FF00FFu;
            e = (e | (e >> 8)) & 0x0000FFFFu;
            const int idx = (int)(__brev(e) >> 20);

            if (lane == 0) out[OUT_OFF_IDX + tok0 + t] = (float)idx;

            // ---- entropy (factorized softmax, MUFU transcendentals) ----
            if (act == 0u) {
                if (lane == 0) atomicAdd(&g_avg[idx], 1.f);
            } else {
                const int k = __popc(act);
                float Z = 1.f;
                unsigned mm = act;
                while (mm) {
                    int b = __ffs(mm) - 1;
                    float ac = __shfl_sync(FULL, a, b);
                    Z *= 1.f + __expf(-ac);
                    mm &= mm - 1;
                }
                const float logZ = __logf(Z);
                const float invZ = 1.f / Z;
                const int   n    = 1 << k;
                for (int base = 0; base < n; base += 32) {
                    const int sub = base + lane;
                    float Asum = 0.f;
                    int   ix   = idx, j = 0;
                    mm = act;
                    while (mm) {
                        int b = __ffs(mm) - 1;
                        int c = b >> 1;
                        float ac = __shfl_sync(FULL, a, b);
                        if ((sub >> j) & 1) { Asum += ac; ix ^= 1 << (11 - c); }
                        mm &= mm - 1; j++;
                    }
                    if (sub < n) {
                        float pp = invZ * __expf(-Asum);
                        pse_acc += pp * fminf(Asum + logZ, LOG_EPS_NEG);
                        atomicAdd(&g_avg[ix], pp);
                    }
                }
            }

            // ---- sparse out-projection ----
            const int pc = __popc((unsigned)idx);
            unsigned bits = (pc <= 6) ? (unsigned)idx : (~(unsigned)idx & 0xFFFu);
            const float* bb = (pc <= 6) ? s_bm : s_bp;
            const u64 coef  = pack2(pc <= 6 ? 2.f : -2.f, pc <= 6 ? 2.f : -2.f);

            u64 o[8];
#pragma unroll
            for (int i = 0; i < 8; i++) o[i] = 0ull;
            while (bits) {
                int b = __ffs(bits) - 1;
                int c = 11 - b;
                const ulonglong2* W = WT2 + c * 128;
#pragma unroll
                for (int i = 0; i < 4; i++) {
                    ulonglong2 w = W[i * 32 + lane];
                    o[2 * i]     = add2(o[2 * i],     w.x);
                    o[2 * i + 1] = add2(o[2 * i + 1], w.y);
                }
                bits &= bits - 1;
            }
            const ulonglong2* B2 = (const ulonglong2*)bb;
#pragma unroll
            for (int i = 0; i < 4; i++) {
                ulonglong2 bv = B2[i * 32 + lane];
                ulonglong2 res;
                res.x = fma2(coef, o[2 * i],     bv.x);
                res.y = fma2(coef, o[2 * i + 1], bv.y);
                O2[(size_t)(tok0 + t) * 128 + i * 32 + lane] = res;
            }
        }
    }

    // ---- reduce pse: warp, then block, then global ----
    pse_acc += __shfl_xor_sync(FULL, pse_acc, 16);
    pse_acc += __shfl_xor_sync(FULL, pse_acc, 8);
    pse_acc += __shfl_xor_sync(FULL, pse_acc, 4);
    pse_acc += __shfl_xor_sync(FULL, pse_acc, 2);
    pse_acc += __shfl_xor_sync(FULL, pse_acc, 1);

    __syncthreads();                 // weights dead past here; reuse s_bm
    if (lane == 0) s_bm[wid] = pse_acc;
    __syncthreads();
    if (wid == 0) {
        float v = (lane < (BLK >> 5)) ? s_bm[lane] : 0.f;
        v += __shfl_xor_sync(FULL, v, 4);
        v += __shfl_xor_sync(FULL, v, 2);
        v += __shfl_xor_sync(FULL, v, 1);
        if (lane == 0) atomicAdd(&g_pse, v);
    }

    // ---- last-block finalize ----
    __threadfence();
    __syncthreads();
    if (threadIdx.x == 0) {
        int old = atomicAdd(&g_cnt, 1);
        s_last = (old == (int)gridDim.x - 1) ? 1 : 0;
    }
    __syncthreads();
    if (s_last) {
        __threadfence();
        const float inv = 1.f / (float)NTOK;
        float ce = 0.f;
        for (int i = threadIdx.x; i < CSIZE; i += BLK) {
            float ap = __ldcg(&g_avg[i]) * inv;
            ce += -ap * __logf(fmaxf(ap, 1e-5f));
        }
        float* red = s_wt;           // reuse smem
        red[threadIdx.x] = ce;
        __syncthreads();
        for (int s = BLK / 2; s > 0; s >>= 1) {
            if (threadIdx.x < (unsigned)s) red[threadIdx.x] += red[threadIdx.x + s];
            __syncthreads();
        }
        if (threadIdx.x == 0) {
            float aux = (__ldcg(&g_pse) * inv - red[0]) * 0.1f;
            out[OUT_OFF_AUX] = aux;
            g_cnt  = 0;
            g_flag = 0;
        }
    }
}

// ---------------------------------------------------------------------------
extern "C" void kernel_launch(void* const* d_in, const int* in_sizes, int n_in,
                              void* d_out, int out_size)
{
    const float* x     = (const float*)d_in[0];
    const float* w_in  = (const float*)d_in[1];
    const float* b_in  = (const float*)d_in[2];
    const float* w_out = (const float*)d_in[3];
    const float* b_out = (const float*)d_in[4];
    float* out = (float*)d_out;

    mainK<<<GRID, BLK>>>(x, w_in, b_in, w_out, b_out, out);
}

// round 12
// speedup vs baseline: 1.6407x; 1.1071x over previous
#include <cuda_runtime.h>

#define DIM   512
#define CDIM  12
#define NTOK  16384
#define CSIZE 4096
#define GRID  592                 // 148 SMs x 4 CTAs: perfectly balanced wave
#define BLK   224                 // 7 warps
#define NWARP 7
#define NWORK 4096                // warp work units (4 tokens each)
#define NPASS 2

#define OUT_OFF_IDX (NTOK * DIM)            // 8388608
#define OUT_OFF_AUX (OUT_OFF_IDX + NTOK)    // 8404992
#define LOG_EPS_NEG 11.512925464970229f     // -ln(1e-5)
#define A_MAX       20.723265837f           // ln(1e9)
#define FULL        0xffffffffu

// ---- device scratch (no allocations allowed) ----
__device__ float g_avg[CSIZE];
__device__ float g_pse;
__device__ int   g_flag = 0;
__device__ int   g_cnt  = 0;

typedef unsigned long long u64;

__device__ __forceinline__ u64 fma2(u64 a, u64 b, u64 c) {
    u64 d; asm("fma.rn.f32x2 %0, %1, %2, %3;" : "=l"(d) : "l"(a), "l"(b), "l"(c));
    return d;
}
__device__ __forceinline__ u64 add2(u64 a, u64 b) {
    u64 d; asm("add.rn.f32x2 %0, %1, %2;" : "=l"(d) : "l"(a), "l"(b));
    return d;
}
__device__ __forceinline__ u64 pack2(float lo, float hi) {
    u64 d; asm("mov.b64 %0, {%1, %2};" : "=l"(d) : "f"(lo), "f"(hi));
    return d;
}
__device__ __forceinline__ float fold2(u64 v) {   // lo + hi
    float lo, hi; asm("mov.b64 {%0, %1}, %2;" : "=f"(lo), "=f"(hi) : "l"(v));
    return lo + hi;
}

// ---------------------------------------------------------------------------
// R11 kernel (39.0us) with perfectly balanced launch: 592 x 224 = 148 SMs x
// 4 CTAs x 7 warps, every SM identical load (28 warp-units). Per-warp math,
// layout, and traffic byte-identical to R11; surplus 48 warps skip to the
// reductions. 4 tokens/warp (2 passes x 2).
// ---------------------------------------------------------------------------
__global__ void __launch_bounds__(BLK, 4)
mainK(const float* __restrict__ x,
      const float* __restrict__ w_in,
      const float* __restrict__ b_in,
      const float* __restrict__ w_out,
      const float* __restrict__ b_out,
      float* __restrict__ out)
{
    __shared__ float s_wt[CDIM * DIM];   // w_out transposed [c][d]
    __shared__ float s_bm[DIM];          // b_out - S
    __shared__ float s_bp[DIM];          // b_out + S
    __shared__ int   s_last;

    if (blockIdx.x == 0) {
        for (int i = threadIdx.x; i < CSIZE; i += BLK) g_avg[i] = 0.f;
        if (threadIdx.x == 0) g_pse = 0.f;
    }

    // stage: transpose w_out, build b_out -+ S  (S = sum_c w_out[d][c])
    for (int d = threadIdx.x; d < DIM; d += BLK) {
        float S = 0.f;
#pragma unroll
        for (int c = 0; c < CDIM; c++) {
            float w = w_out[d * CDIM + c];
            s_wt[c * DIM + d] = w;
            S += w;
        }
        float b = b_out[d];
        s_bm[d] = b - S;
        s_bp[d] = b + S;
    }
    __syncthreads();

    if (blockIdx.x == 0 && threadIdx.x == 0) {
        __threadfence();
        atomicExch(&g_flag, 1);
    }

    const int wid   = threadIdx.x >> 5;
    const int lane  = threadIdx.x & 31;
    const int gw    = blockIdx.x * NWARP + wid;        // 0..4143
    const int c_own = (lane >> 1) & 15;                // c owned by this lane
    const float b_lane = (c_own < CDIM) ? __ldg(&b_in[c_own]) : 0.f;

    const ulonglong2* X2  = (const ulonglong2*)x;
    const ulonglong2* W2  = (const ulonglong2*)w_in;
    const ulonglong2* WT2 = (const ulonglong2*)s_wt;
    ulonglong2*       O2  = (ulonglong2*)out;

    float pse_acc = 0.f;      // distributed across all lanes
    bool  flagged = false;

    if (gw < NWORK) {
#pragma unroll
    for (int p = 0; p < NPASS; p++) {
        const int tok0 = gw * 4 + p * 2;

        // ---- in-projection: packed FFMA2, chunked over c (6 at a time) ----
        float vv[2][CDIM];
#pragma unroll
        for (int ch = 0; ch < 2; ch++) {
            u64 a2[2][6];
#pragma unroll
            for (int cc = 0; cc < 6; cc++) { a2[0][cc] = 0ull; a2[1][cc] = 0ull; }
#pragma unroll
            for (int i = 0; i < 4; i++) {
                const int off = i * 32 + lane;
                ulonglong2 x0 = X2[(size_t)tok0 * 128 + off];
                ulonglong2 x1 = X2[(size_t)(tok0 + 1) * 128 + off];
#pragma unroll
                for (int cc = 0; cc < 6; cc++) {
                    ulonglong2 w = W2[(ch * 6 + cc) * 128 + off];
                    a2[0][cc] = fma2(x0.x, w.x, a2[0][cc]);
                    a2[0][cc] = fma2(x0.y, w.y, a2[0][cc]);
                    a2[1][cc] = fma2(x1.x, w.x, a2[1][cc]);
                    a2[1][cc] = fma2(x1.y, w.y, a2[1][cc]);
                }
            }
#pragma unroll
            for (int cc = 0; cc < 6; cc++) {
                vv[0][ch * 6 + cc] = fold2(a2[0][cc]);
                vv[1][ch * 6 + cc] = fold2(a2[1][cc]);
            }
        }

        if (!flagged) {
            while (*(volatile int*)&g_flag == 0) { }
            flagged = true;
        }

        // ---- per-token: reduce-scatter -> ballots -> entropy -> out-proj ----
#pragma unroll
        for (int t = 0; t < 2; t++) {
            // reduce-scatter: sum over lanes; c lands on lanes 2c, 2c+1.
            float r8[8];
#pragma unroll
            for (int j = 0; j < 8; j++) {
                float hiV  = (j + 8 < CDIM) ? vv[t][j + 8] : 0.f;
                float send = (lane & 16) ? vv[t][j] : hiV;
                float keep = (lane & 16) ? hiV : vv[t][j];
                r8[j] = keep + __shfl_xor_sync(FULL, send, 16);
            }
            float r4[4];
#pragma unroll
            for (int j = 0; j < 4; j++) {
                float send = (lane & 8) ? r8[j] : r8[j + 4];
                float keep = (lane & 8) ? r8[j + 4] : r8[j];
                r4[j] = keep + __shfl_xor_sync(FULL, send, 8);
            }
            float r2[2];
#pragma unroll
            for (int j = 0; j < 2; j++) {
                float send = (lane & 4) ? r4[j] : r4[j + 2];
                float keep = (lane & 4) ? r4[j + 2] : r4[j];
                r2[j] = keep + __shfl_xor_sync(FULL, send, 4);
            }
            float send = (lane & 2) ? r2[0] : r2[1];
            float keep = (lane & 2) ? r2[1] : r2[0];
            float r1 = keep + __shfl_xor_sync(FULL, send, 2);
            r1 += __shfl_xor_sync(FULL, r1, 1);

            const float xp = r1 + b_lane;               // xp for c_own
            const float a  = 400.f * fabsf(xp);

            unsigned sb  = __ballot_sync(FULL, xp > 0.f);
            unsigned act = __ballot_sync(FULL, a < A_MAX) & 0x00555555u;

            // index: compress even bits of sb (bit 2c -> bit c), then reverse
            unsigned e = sb & 0x00555555u;
            e = (e | (e >> 1)) & 0x33333333u;
            e = (e | (e >> 2)) & 0x0F0F0F0Fu;
            e = (e | (e >> 4)) & 0x00FF00FFu;
            e = (e | (e >> 8)) & 0x0000FFFFu;
            const int idx = (int)(__brev(e) >> 20);

            if (lane == 0) out[OUT_OFF_IDX + tok0 + t] = (float)idx;

            // ---- entropy (factorized softmax, MUFU transcendentals) ----
            if (act == 0u) {
                if (lane == 0) atomicAdd(&g_avg[idx], 1.f);
            } else {
                const int k = __popc(act);
                float Z = 1.f;
                unsigned mm = act;
                while (mm) {
                    int b = __ffs(mm) - 1;
                    float ac = __shfl_sync(FULL, a, b);
                    Z *= 1.f + __expf(-ac);
                    mm &= mm - 1;
                }
                const float logZ = __logf(Z);
                const float invZ = 1.f / Z;
                const int   n    = 1 << k;
                for (int base = 0; base < n; base += 32) {
                    const int sub = base + lane;
                    float Asum = 0.f;
                    int   ix   = idx, j = 0;
                    mm = act;
                    while (mm) {
                        int b = __ffs(mm) - 1;
                        int c = b >> 1;
                        float ac = __shfl_sync(FULL, a, b);
                        if ((sub >> j) & 1) { Asum += ac; ix ^= 1 << (11 - c); }
                        mm &= mm - 1; j++;
                    }
                    if (sub < n) {
                        float pp = invZ * __expf(-Asum);
                        pse_acc += pp * fminf(Asum + logZ, LOG_EPS_NEG);
                        atomicAdd(&g_avg[ix], pp);
                    }
                }
            }

            // ---- sparse out-projection ----
            const int pc = __popc((unsigned)idx);
            unsigned bits = (pc <= 6) ? (unsigned)idx : (~(unsigned)idx & 0xFFFu);
            const float* bb = (pc <= 6) ? s_bm : s_bp;
            const u64 coef  = pack2(pc <= 6 ? 2.f : -2.f, pc <= 6 ? 2.f : -2.f);

            u64 o[8];
#pragma unroll
            for (int i = 0; i < 8; i++) o[i] = 0ull;
            while (bits) {
                int b = __ffs(bits) - 1;
                int c = 11 - b;
                const ulonglong2* W = WT2 + c * 128;
#pragma unroll
                for (int i = 0; i < 4; i++) {
                    ulonglong2 w = W[i * 32 + lane];
                    o[2 * i]     = add2(o[2 * i],     w.x);
                    o[2 * i + 1] = add2(o[2 * i + 1], w.y);
                }
                bits &= bits - 1;
            }
            const ulonglong2* B2 = (const ulonglong2*)bb;
#pragma unroll
            for (int i = 0; i < 4; i++) {
                ulonglong2 bv = B2[i * 32 + lane];
                ulonglong2 res;
                res.x = fma2(coef, o[2 * i],     bv.x);
                res.y = fma2(coef, o[2 * i + 1], bv.y);
                O2[(size_t)(tok0 + t) * 128 + i * 32 + lane] = res;
            }
        }
    }
    }  // gw < NWORK

    // ---- reduce pse: warp, then block, then global ----
    pse_acc += __shfl_xor_sync(FULL, pse_acc, 16);
    pse_acc += __shfl_xor_sync(FULL, pse_acc, 8);
    pse_acc += __shfl_xor_sync(FULL, pse_acc, 4);
    pse_acc += __shfl_xor_sync(FULL, pse_acc, 2);
    pse_acc += __shfl_xor_sync(FULL, pse_acc, 1);

    __syncthreads();                 // weights dead past here; reuse s_bm
    if (lane == 0) s_bm[wid] = pse_acc;
    __syncthreads();
    if (wid == 0) {
        float v = (lane < NWARP) ? s_bm[lane] : 0.f;
        v += __shfl_xor_sync(FULL, v, 4);
        v += __shfl_xor_sync(FULL, v, 2);
        v += __shfl_xor_sync(FULL, v, 1);
        if (lane == 0) atomicAdd(&g_pse, v);
    }

    // ---- last-block finalize ----
    __threadfence();
    __syncthreads();
    if (threadIdx.x == 0) {
        int old = atomicAdd(&g_cnt, 1);
        s_last = (old == (int)gridDim.x - 1) ? 1 : 0;
    }
    __syncthreads();
    if (s_last) {
        __threadfence();
        const float inv = 1.f / (float)NTOK;
        float ce = 0.f;
        for (int i = threadIdx.x; i < CSIZE; i += BLK) {
            float ap = __ldcg(&g_avg[i]) * inv;
            ce += -ap * __logf(fmaxf(ap, 1e-5f));
        }
        float* red = s_wt;           // reuse smem
        red[threadIdx.x] = ce;
        __syncthreads();
        for (int s = 128; s > 0; s >>= 1) {
            if (threadIdx.x < (unsigned)s && threadIdx.x + s < BLK)
                red[threadIdx.x] += red[threadIdx.x + s];
            __syncthreads();
        }
        if (threadIdx.x == 0) {
            float aux = (__ldcg(&g_pse) * inv - red[0]) * 0.1f;
            out[OUT_OFF_AUX] = aux;
            g_cnt  = 0;
            g_flag = 0;
        }
    }
}

// ---------------------------------------------------------------------------
extern "C" void kernel_launch(void* const* d_in, const int* in_sizes, int n_in,
                              void* d_out, int out_size)
{
    const float* x     = (const float*)d_in[0];
    const float* w_in  = (const float*)d_in[1];
    const float* b_in  = (const float*)d_in[2];
    const float* w_out = (const float*)d_in[3];
    const float* b_out = (const float*)d_in[4];
    float* out = (float*)d_out;

    mainK<<<GRID, BLK>>>(x, w_in, b_in, w_out, b_out, out);
}

// round 15
// speedup vs baseline: 1.6572x; 1.0101x over previous
#include <cuda_runtime.h>

#define DIM   512
#define CDIM  12
#define NTOK  16384
#define CSIZE 4096
#define GRID  592                 // 148 SMs x 4 CTAs: perfectly balanced wave
#define BLK   224                 // 7 warps
#define NWARP 7
#define NWORK 4096                // warp work units (4 tokens each)
#define NPASS 2

#define OUT_OFF_IDX (NTOK * DIM)            // 8388608
#define OUT_OFF_AUX (OUT_OFF_IDX + NTOK)    // 8404992
#define LOG_EPS_NEG 11.512925464970229f     // -ln(1e-5)
#define A_MAX       20.723265837f           // ln(1e9)
#define FULL        0xffffffffu

// ---- device scratch (no allocations allowed) ----
__device__ float g_avg[CSIZE];
__device__ float g_pse;
__device__ int   g_flag = 0;
__device__ int   g_cnt  = 0;

typedef unsigned long long u64;

__device__ __forceinline__ u64 fma2(u64 a, u64 b, u64 c) {
    u64 d; asm("fma.rn.f32x2 %0, %1, %2, %3;" : "=l"(d) : "l"(a), "l"(b), "l"(c));
    return d;
}
__device__ __forceinline__ u64 add2(u64 a, u64 b) {
    u64 d; asm("add.rn.f32x2 %0, %1, %2;" : "=l"(d) : "l"(a), "l"(b));
    return d;
}
__device__ __forceinline__ u64 pack2(float lo, float hi) {
    u64 d; asm("mov.b64 %0, {%1, %2};" : "=l"(d) : "f"(lo), "f"(hi));
    return d;
}
__device__ __forceinline__ float fold2(u64 v) {   // lo + hi
    float lo, hi; asm("mov.b64 {%0, %1}, %2;" : "=f"(lo), "=f"(hi) : "l"(v));
    return lo + hi;
}

// ---------------------------------------------------------------------------
// R12 (35.3us best) + two latency cuts, traffic/summation byte-identical:
//   (1) L2 prefetch of pass-2 x (one predicated line per lane, zero regs)
//   (2) two-token reduce-scatter interleaved level-major (ILP 2 on the
//       5-level SHFL chain; same per-token pairwise tree -> identical sums)
// 592 x 224 (148 SMs x 4 CTAs x 7 warps, perfectly balanced), 4 tokens/warp.
// ---------------------------------------------------------------------------
__global__ void __launch_bounds__(BLK, 4)
mainK(const float* __restrict__ x,
      const float* __restrict__ w_in,
      const float* __restrict__ b_in,
      const float* __restrict__ w_out,
      const float* __restrict__ b_out,
      float* __restrict__ out)
{
    __shared__ float s_wt[CDIM * DIM];   // w_out transposed [c][d]
    __shared__ float s_bm[DIM];          // b_out - S
    __shared__ float s_bp[DIM];          // b_out + S
    __shared__ int   s_last;

    if (blockIdx.x == 0) {
        for (int i = threadIdx.x; i < CSIZE; i += BLK) g_avg[i] = 0.f;
        if (threadIdx.x == 0) g_pse = 0.f;
    }

    const int wid   = threadIdx.x >> 5;
    const int lane  = threadIdx.x & 31;
    const int gw    = blockIdx.x * NWARP + wid;        // 0..4143

    // (1) L2-prefetch pass-2's x (tokens gw*4+2, gw*4+3: 4KB = 32 x 128B)
    if (gw < NWORK) {
        const char* pf = (const char*)(x + (size_t)(gw * 4 + 2) * DIM);
        asm volatile("prefetch.global.L2 [%0];" :: "l"(pf + lane * 128));
    }

    // stage: transpose w_out, build b_out -+ S  (S = sum_c w_out[d][c])
    for (int d = threadIdx.x; d < DIM; d += BLK) {
        float S = 0.f;
#pragma unroll
        for (int c = 0; c < CDIM; c++) {
            float w = w_out[d * CDIM + c];
            s_wt[c * DIM + d] = w;
            S += w;
        }
        float b = b_out[d];
        s_bm[d] = b - S;
        s_bp[d] = b + S;
    }
    __syncthreads();

    if (blockIdx.x == 0 && threadIdx.x == 0) {
        __threadfence();
        atomicExch(&g_flag, 1);
    }

    const int c_own = (lane >> 1) & 15;                // c owned by this lane
    const float b_lane = (c_own < CDIM) ? __ldg(&b_in[c_own]) : 0.f;

    const ulonglong2* X2  = (const ulonglong2*)x;
    const ulonglong2* W2  = (const ulonglong2*)w_in;
    const ulonglong2* WT2 = (const ulonglong2*)s_wt;
    ulonglong2*       O2  = (ulonglong2*)out;

    float pse_acc = 0.f;      // distributed across all lanes
    bool  flagged = false;

    if (gw < NWORK) {
#pragma unroll
    for (int p = 0; p < NPASS; p++) {
        const int tok0 = gw * 4 + p * 2;

        // ---- in-projection: packed FFMA2, chunked over c (6 at a time) ----
        float vv[2][CDIM];
#pragma unroll
        for (int ch = 0; ch < 2; ch++) {
            u64 a2[2][6];
#pragma unroll
            for (int cc = 0; cc < 6; cc++) { a2[0][cc] = 0ull; a2[1][cc] = 0ull; }
#pragma unroll
            for (int i = 0; i < 4; i++) {
                const int off = i * 32 + lane;
                ulonglong2 x0 = X2[(size_t)tok0 * 128 + off];
                ulonglong2 x1 = X2[(size_t)(tok0 + 1) * 128 + off];
#pragma unroll
                for (int cc = 0; cc < 6; cc++) {
                    ulonglong2 w = W2[(ch * 6 + cc) * 128 + off];
                    a2[0][cc] = fma2(x0.x, w.x, a2[0][cc]);
                    a2[0][cc] = fma2(x0.y, w.y, a2[0][cc]);
                    a2[1][cc] = fma2(x1.x, w.x, a2[1][cc]);
                    a2[1][cc] = fma2(x1.y, w.y, a2[1][cc]);
                }
            }
#pragma unroll
            for (int cc = 0; cc < 6; cc++) {
                vv[0][ch * 6 + cc] = fold2(a2[0][cc]);
                vv[1][ch * 6 + cc] = fold2(a2[1][cc]);
            }
        }

        if (!flagged) {
            while (*(volatile int*)&g_flag == 0) { }
            flagged = true;
        }

        // ---- (2) reduce-scatter, BOTH tokens interleaved level-major ----
        float r8[2][8];
#pragma unroll
        for (int j = 0; j < 8; j++)
#pragma unroll
            for (int t = 0; t < 2; t++) {
                float hiV  = (j + 8 < CDIM) ? vv[t][j + 8] : 0.f;
                float send = (lane & 16) ? vv[t][j] : hiV;
                float keep = (lane & 16) ? hiV : vv[t][j];
                r8[t][j] = keep + __shfl_xor_sync(FULL, send, 16);
            }
        float r4[2][4];
#pragma unroll
        for (int j = 0; j < 4; j++)
#pragma unroll
            for (int t = 0; t < 2; t++) {
                float send = (lane & 8) ? r8[t][j] : r8[t][j + 4];
                float keep = (lane & 8) ? r8[t][j + 4] : r8[t][j];
                r4[t][j] = keep + __shfl_xor_sync(FULL, send, 8);
            }
        float r2[2][2];
#pragma unroll
        for (int j = 0; j < 2; j++)
#pragma unroll
            for (int t = 0; t < 2; t++) {
                float send = (lane & 4) ? r4[t][j] : r4[t][j + 2];
                float keep = (lane & 4) ? r4[t][j + 2] : r4[t][j];
                r2[t][j] = keep + __shfl_xor_sync(FULL, send, 4);
            }
        float aa2[2];
        int   idx2[2];
        unsigned act2[2];
#pragma unroll
        for (int t = 0; t < 2; t++) {
            float send = (lane & 2) ? r2[t][0] : r2[t][1];
            float keep = (lane & 2) ? r2[t][1] : r2[t][0];
            float r1 = keep + __shfl_xor_sync(FULL, send, 2);
            r1 += __shfl_xor_sync(FULL, r1, 1);

            const float xp = r1 + b_lane;               // xp for c_own
            aa2[t] = 400.f * fabsf(xp);

            unsigned sb = __ballot_sync(FULL, xp > 0.f);
            act2[t]     = __ballot_sync(FULL, aa2[t] < A_MAX) & 0x00555555u;

            // index: compress even bits of sb (bit 2c -> bit c), then reverse
            unsigned e = sb & 0x00555555u;
            e = (e | (e >> 1)) & 0x33333333u;
            e = (e | (e >> 2)) & 0x0F0F0F0Fu;
            e = (e | (e >> 4)) & 0x00FF00FFu;
            e = (e | (e >> 8)) & 0x0000FFFFu;
            idx2[t] = (int)(__brev(e) >> 20);

            if (lane == 0) out[OUT_OFF_IDX + tok0 + t] = (float)idx2[t];
        }

        // ---- per-token: entropy -> out-proj ----
#pragma unroll
        for (int t = 0; t < 2; t++) {
            const float    a   = aa2[t];
            const unsigned act = act2[t];
            const int      idx = idx2[t];

            // ---- entropy (factorized softmax, MUFU transcendentals) ----
            if (act == 0u) {
                if (lane == 0) atomicAdd(&g_avg[idx], 1.f);
            } else {
                const int k = __popc(act);
                float Z = 1.f;
                unsigned mm = act;
                while (mm) {
                    int b = __ffs(mm) - 1;
                    float ac = __shfl_sync(FULL, a, b);
                    Z *= 1.f + __expf(-ac);
                    mm &= mm - 1;
                }
                const float logZ = __logf(Z);
                const float invZ = 1.f / Z;
                const int   n    = 1 << k;
                for (int base = 0; base < n; base += 32) {
                    const int sub = base + lane;
                    float Asum = 0.f;
                    int   ix   = idx, j = 0;
                    mm = act;
                    while (mm) {
                        int b = __ffs(mm) - 1;
                        int c = b >> 1;
                        float ac = __shfl_sync(FULL, a, b);
                        if ((sub >> j) & 1) { Asum += ac; ix ^= 1 << (11 - c); }
                        mm &= mm - 1; j++;
                    }
                    if (sub < n) {
                        float pp = invZ * __expf(-Asum);
                        pse_acc += pp * fminf(Asum + logZ, LOG_EPS_NEG);
                        atomicAdd(&g_avg[ix], pp);
                    }
                }
            }

            // ---- sparse out-projection ----
            const int pc = __popc((unsigned)idx);
            unsigned bits = (pc <= 6) ? (unsigned)idx : (~(unsigned)idx & 0xFFFu);
            const float* bb = (pc <= 6) ? s_bm : s_bp;
            const u64 coef  = pack2(pc <= 6 ? 2.f : -2.f, pc <= 6 ? 2.f : -2.f);

            u64 o[8];
#pragma unroll
            for (int i = 0; i < 8; i++) o[i] = 0ull;
            while (bits) {
                int b = __ffs(bits) - 1;
                int c = 11 - b;
                const ulonglong2* W = WT2 + c * 128;
#pragma unroll
                for (int i = 0; i < 4; i++) {
                    ulonglong2 w = W[i * 32 + lane];
                    o[2 * i]     = add2(o[2 * i],     w.x);
                    o[2 * i + 1] = add2(o[2 * i + 1], w.y);
                }
                bits &= bits - 1;
            }
            const ulonglong2* B2 = (const ulonglong2*)bb;
#pragma unroll
            for (int i = 0; i < 4; i++) {
                ulonglong2 bv = B2[i * 32 + lane];
                ulonglong2 res;
                res.x = fma2(coef, o[2 * i],     bv.x);
                res.y = fma2(coef, o[2 * i + 1], bv.y);
                O2[(size_t)(tok0 + t) * 128 + i * 32 + lane] = res;
            }
        }
    }
    }  // gw < NWORK

    // ---- reduce pse: warp, then block, then global ----
    pse_acc += __shfl_xor_sync(FULL, pse_acc, 16);
    pse_acc += __shfl_xor_sync(FULL, pse_acc, 8);
    pse_acc += __shfl_xor_sync(FULL, pse_acc, 4);
    pse_acc += __shfl_xor_sync(FULL, pse_acc, 2);
    pse_acc += __shfl_xor_sync(FULL, pse_acc, 1);

    __syncthreads();                 // weights dead past here; reuse s_bm
    if (lane == 0) s_bm[wid] = pse_acc;
    __syncthreads();
    if (wid == 0) {
        float v = (lane < NWARP) ? s_bm[lane] : 0.f;
        v += __shfl_xor_sync(FULL, v, 4);
        v += __shfl_xor_sync(FULL, v, 2);
        v += __shfl_xor_sync(FULL, v, 1);
        if (lane == 0) atomicAdd(&g_pse, v);
    }

    // ---- last-block finalize ----
    __threadfence();
    __syncthreads();
    if (threadIdx.x == 0) {
        int old = atomicAdd(&g_cnt, 1);
        s_last = (old == (int)gridDim.x - 1) ? 1 : 0;
    }
    __syncthreads();
    if (s_last) {
        __threadfence();
        const float inv = 1.f / (float)NTOK;
        float ce = 0.f;
        for (int i = threadIdx.x; i < CSIZE; i += BLK) {
            float ap = __ldcg(&g_avg[i]) * inv;
            ce += -ap * __logf(fmaxf(ap, 1e-5f));
        }
        float* red = s_wt;           // reuse smem
        red[threadIdx.x] = ce;
        __syncthreads();
        for (int s = 128; s > 0; s >>= 1) {
            if (threadIdx.x < (unsigned)s && threadIdx.x + s < BLK)
                red[threadIdx.x] += red[threadIdx.x + s];
            __syncthreads();
        }
        if (threadIdx.x == 0) {
            float aux = (__ldcg(&g_pse) * inv - red[0]) * 0.1f;
            out[OUT_OFF_AUX] = aux;
            g_cnt  = 0;
            g_flag = 0;
        }
    }
}

// ---------------------------------------------------------------------------
extern "C" void kernel_launch(void* const* d_in, const int* in_sizes, int n_in,
                              void* d_out, int out_size)
{
    const float* x     = (const float*)d_in[0];
    const float* w_in  = (const float*)d_in[1];
    const float* b_in  = (const float*)d_in[2];
    const float* w_out = (const float*)d_in[3];
    const float* b_out = (const float*)d_in[4];
    float* out = (float*)d_out;

    mainK<<<GRID, BLK>>>(x, w_in, b_in, w_out, b_out, out);
}